// round 10
// baseline (speedup 1.0000x reference)
#include <cuda_runtime.h>
#include <cuda_fp16.h>
#include <cstdint>

// Problem dims
#define IN_F   4096
#define OUT_F  16384
#define MROWS  2048

// GEMM tiling: BM=128, BN=256, BK=64 (fp16 -> 128B rows), 3-stage pipeline
// Warp grid 2(m) x 4(n) -> warp tile 64x64 (ldsm:HMMA = 8:32 per k16-step)
static constexpr int BM = 128;
static constexpr int BN = 256;
static constexpr int BK = 64;
static constexpr int KITERS = IN_F / BK;                 // 64
static constexpr int A_TILE = BM * BK * 2;               // 16 KB
static constexpr int B_TILE = BN * BK * 2;               // 32 KB
static constexpr int STAGE_BYTES = A_TILE + B_TILE;      // 48 KB
static constexpr int STAGES = 3;
static constexpr int SMEM_TOTAL = STAGES * STAGE_BYTES;  // 147456 -> 1 CTA/SM

// Combined prep kernel split point
static constexpr int XBLOCKS = ((size_t)MROWS * IN_F) / (256 * 8);    // 4096
static constexpr int WBLOCKS = ((size_t)OUT_F * IN_F) / (256 * 16);   // 16384

// ── Scratch (device globals; no allocation) ──────────────────────────────
__device__ __half g_X16[(size_t)MROWS * IN_F];
__device__ __half g_W16[(size_t)OUT_F * IN_F];

// ── PTX helpers (sm_80-level only; family-portable) ──────────────────────
__device__ __forceinline__ uint32_t smem_u32(const void* p) {
    uint32_t a;
    asm("{ .reg .u64 t; cvta.to.shared.u64 t, %1; cvt.u32.u64 %0, t; }" : "=r"(a) : "l"(p));
    return a;
}
#define CP_ASYNC16(dst, src) \
    asm volatile("cp.async.cg.shared.global [%0], [%1], 16;" :: "r"(dst), "l"(src))
#define CP_COMMIT() asm volatile("cp.async.commit_group;" ::: "memory")
#define CP_WAIT1()  asm volatile("cp.async.wait_group 1;" ::: "memory")

__device__ __forceinline__ void ldsm4(uint32_t& r0, uint32_t& r1, uint32_t& r2, uint32_t& r3,
                                      uint32_t addr) {
    asm volatile("ldmatrix.sync.aligned.m8n8.x4.shared.b16 {%0,%1,%2,%3}, [%4];"
                 : "=r"(r0), "=r"(r1), "=r"(r2), "=r"(r3) : "r"(addr));
}
#define HMMA(c, a0, a1, a2, a3, b0, b1)                                       \
    asm volatile("mma.sync.aligned.m16n8k16.row.col.f32.f16.f16.f32 "         \
                 "{%0,%1,%2,%3},{%4,%5,%6,%7},{%8,%9},{%0,%1,%2,%3};"         \
                 : "+f"((c)[0]), "+f"((c)[1]), "+f"((c)[2]), "+f"((c)[3])     \
                 : "r"(a0), "r"(a1), "r"(a2), "r"(a3), "r"(b0), "r"(b1))

// swizzled byte offset of (row, 16B-chunk) inside a rows x 128B tile
__device__ __forceinline__ uint32_t swz(uint32_t row, uint32_t chunk) {
    return row * 128u + ((chunk ^ (row & 7u)) << 4);
}

// ── Combined prep: x fp32->fp16, W16 = ternary * fp16(scale) ─────────────
__global__ void prep_kernel(const float* __restrict__ x,
                            const int* __restrict__ tern,
                            const float* __restrict__ scales) {
    int b = blockIdx.x;
    if (b < XBLOCKS) {
        size_t i = ((size_t)b * blockDim.x + threadIdx.x) * 8;
        const float4* x4 = reinterpret_cast<const float4*>(x + i);
        float4 a = x4[0], c = x4[1];
        float v[8] = {a.x, a.y, a.z, a.w, c.x, c.y, c.z, c.w};
        union { __half h[8]; uint4 u; } o;
#pragma unroll
        for (int j = 0; j < 8; j++) o.h[j] = __float2half(v[j]);
        *reinterpret_cast<uint4*>(&g_X16[i]) = o.u;
    } else {
        size_t i = ((size_t)(b - XBLOCKS) * blockDim.x + threadIdx.x) * 16;
        const int4* t4 = reinterpret_cast<const int4*>(tern + i);
        // all 16 elems lie in one 128-wide scale group (i is a multiple of 16)
        float sf = __half2float(__float2half(scales[i >> 7]));
        union { __half h[16]; uint4 u[2]; } o;
#pragma unroll
        for (int q = 0; q < 4; q++) {
            int4 t = t4[q];
            o.h[q * 4 + 0] = __float2half(sf * (float)t.x);  // exact: t in {-1,0,1}
            o.h[q * 4 + 1] = __float2half(sf * (float)t.y);
            o.h[q * 4 + 2] = __float2half(sf * (float)t.z);
            o.h[q * 4 + 3] = __float2half(sf * (float)t.w);
        }
        uint4* dst = reinterpret_cast<uint4*>(&g_W16[i]);
        dst[0] = o.u[0];
        dst[1] = o.u[1];
    }
}

// ── GEMM: out[M,N] = X16 @ W16^T, fp32 accum in HMMA ─────────────────────
extern __shared__ __align__(128) char smem_raw[];

__global__ void __launch_bounds__(256, 1) qsgd_gemm(float* __restrict__ out)
{
    uint32_t sb = smem_u32(smem_raw);

    int tid = threadIdx.x, lane = tid & 31, wid = tid >> 5;
    int wm = wid & 1, wn = wid >> 1;          // warp grid 2(m) x 4(n): warp tile 64x64
    int gID = lane >> 2, tig = lane & 3;
    int mt0 = blockIdx.x, nt0 = blockIdx.y;   // m fastest in grid

    // ---- cp.async addressing: thread t -> row (t>>3) + 32j, chunk t&7 (bytes)
    int ld_row = tid >> 3, ld_chunk = tid & 7;
    const int8_t* gA = reinterpret_cast<const int8_t*>(g_X16) +
                       (size_t)(mt0 * BM + ld_row) * (IN_F * 2) + ld_chunk * 16;
    const int8_t* gB = reinterpret_cast<const int8_t*>(g_W16) +
                       (size_t)(nt0 * BN + ld_row) * (IN_F * 2) + ld_chunk * 16;
    uint32_t st_off[8];
#pragma unroll
    for (int j = 0; j < 8; j++) st_off[j] = swz(ld_row + 32 * j, ld_chunk);

    // ---- ldmatrix per-lane address components
    // A x4 (m16 x k16): row = wm*64 + mt*16 + (lane&15), chunk bit = lane>>4
    uint32_t a_row_base = wm * 64 + (lane & 15);
    uint32_t a_cbit = (uint32_t)(lane >> 4);
    // B x4 (n16 x k16): row = wn*64 + nb*16 + (lane&7) + ((lane>>4)&1)*8, cbit=(lane>>3)&1
    uint32_t b_row_base = wn * 64 + (lane & 7) + ((lane >> 4) & 1) * 8;
    uint32_t b_cbit = (uint32_t)((lane >> 3) & 1);

    float fa[4][8][4];
#pragma unroll
    for (int mt = 0; mt < 4; mt++)
#pragma unroll
        for (int nt = 0; nt < 8; nt++)
#pragma unroll
            for (int r = 0; r < 4; r++) fa[mt][nt][r] = 0.0f;

    // ---- prologue: stages 0,1
#pragma unroll
    for (int p = 0; p < 2; p++) {
        uint32_t s_a = sb + p * STAGE_BYTES;
        size_t kb = (size_t)p * (BK * 2);
#pragma unroll
        for (int j = 0; j < 4; j++) {
            size_t go = (size_t)(32 * j) * (IN_F * 2) + kb;
            CP_ASYNC16(s_a + st_off[j], gA + go);
        }
#pragma unroll
        for (int j = 0; j < 8; j++) {
            size_t go = (size_t)(32 * j) * (IN_F * 2) + kb;
            CP_ASYNC16(s_a + A_TILE + st_off[j], gB + go);
        }
        CP_COMMIT();
    }

    // ---- main loop: wait -> sync -> issue(it+2) -> compute(it)
    for (int it = 0; it < KITERS; it++) {
        CP_WAIT1();                 // stage `it` complete
        __syncthreads();            // visibility + frees buffer (it+2)%3

        if (it + 2 < KITERS) {
            uint32_t s_a = sb + ((it + 2) % STAGES) * STAGE_BYTES;
            size_t kb = (size_t)(it + 2) * (BK * 2);
#pragma unroll
            for (int j = 0; j < 4; j++) {
                size_t go = (size_t)(32 * j) * (IN_F * 2) + kb;
                CP_ASYNC16(s_a + st_off[j], gA + go);
            }
#pragma unroll
            for (int j = 0; j < 8; j++) {
                size_t go = (size_t)(32 * j) * (IN_F * 2) + kb;
                CP_ASYNC16(s_a + A_TILE + st_off[j], gB + go);
            }
        }
        CP_COMMIT();

        uint32_t sA = sb + (it % STAGES) * STAGE_BYTES;
        uint32_t sB = sA + A_TILE;

        // 4 k16 steps cover BK=64; per step: 4 A-ldsm + 4 B-ldsm, 32 HMMA
#pragma unroll
        for (int ks = 0; ks < 4; ks++) {
            uint32_t af[4][4];
#pragma unroll
            for (int mt = 0; mt < 4; mt++) {
                uint32_t row = a_row_base + mt * 16;
                uint32_t addr = sA + row * 128u + (((2u * ks + a_cbit) ^ (row & 7u)) << 4);
                ldsm4(af[mt][0], af[mt][1], af[mt][2], af[mt][3], addr);
            }
            uint32_t bf[8][2];
#pragma unroll
            for (int nb = 0; nb < 4; nb++) {
                uint32_t row = b_row_base + nb * 16;
                uint32_t addr = sB + row * 128u + (((2u * ks + b_cbit) ^ (row & 7u)) << 4);
                uint32_t r0, r1, r2, r3;
                ldsm4(r0, r1, r2, r3, addr);
                bf[nb * 2 + 0][0] = r0; bf[nb * 2 + 0][1] = r1;
                bf[nb * 2 + 1][0] = r2; bf[nb * 2 + 1][1] = r3;
            }
#pragma unroll
            for (int mt = 0; mt < 4; mt++)
#pragma unroll
                for (int nt = 0; nt < 8; nt++)
                    HMMA(fa[mt][nt], af[mt][0], af[mt][1], af[mt][2], af[mt][3],
                         bf[nt][0], bf[nt][1]);
        }
    }

    // ---- epilogue
#pragma unroll
    for (int mt = 0; mt < 4; mt++)
#pragma unroll
        for (int rr = 0; rr < 2; rr++) {
            int m_g = mt0 * BM + wm * 64 + mt * 16 + gID + rr * 8;
            float* op = out + (size_t)m_g * OUT_F + nt0 * BN + wn * 64 + tig * 2;
#pragma unroll
            for (int nt = 0; nt < 8; nt++) {
                float2 v;
                v.x = fa[mt][nt][rr * 2 + 0];
                v.y = fa[mt][nt][rr * 2 + 1];
                *reinterpret_cast<float2*>(op + nt * 8) = v;
            }
        }
}

// ── Host ─────────────────────────────────────────────────────────────────
extern "C" void kernel_launch(void* const* d_in, const int* in_sizes, int n_in,
                              void* d_out, int out_size) {
    const float* x      = (const float*)d_in[0];
    const int*   tern   = (const int*)d_in[1];
    const float* scales = (const float*)d_in[2];
    float* out = (float*)d_out;

    prep_kernel<<<XBLOCKS + WBLOCKS, 256>>>(x, tern, scales);

    cudaFuncSetAttribute((const void*)qsgd_gemm,
                         cudaFuncAttributeMaxDynamicSharedMemorySize, SMEM_TOTAL);
    // grid: x = M tiles (fastest) so concurrent CTAs share W tiles via L2
    qsgd_gemm<<<dim3(MROWS / BM, OUT_F / BN), 256, SMEM_TOTAL>>>(out);
}

// round 12
// speedup vs baseline: 1.0772x; 1.0772x over previous
#include <cuda_runtime.h>
#include <cuda_fp16.h>
#include <cstdint>

// Problem dims
#define IN_F   4096
#define OUT_F  16384
#define MROWS  2048

// GEMM tiling: BM=128, BN=128, BK=64 (fp16 -> 128B rows), 3-stage pipeline
// Warp grid 2(m) x 4(n) -> warp tile 64x32. 2 CTAs/SM (16 warps, RF-full).
static constexpr int BM = 128;
static constexpr int BN = 128;
static constexpr int BK = 64;
static constexpr int KITERS = IN_F / BK;                 // 64
static constexpr int A_TILE = BM * BK * 2;               // 16 KB
static constexpr int B_TILE = BN * BK * 2;               // 16 KB
static constexpr int STAGE_BYTES = A_TILE + B_TILE;      // 32 KB
static constexpr int STAGES = 3;
static constexpr int SMEM_TOTAL = STAGES * STAGE_BYTES;  // 98304 -> 2 CTAs/SM

// Combined prep kernel split points (x: 16 elems/thread, w: 32 elems/thread)
static constexpr int XBLOCKS = ((size_t)MROWS * IN_F) / (256 * 16);   // 2048
static constexpr int WBLOCKS = ((size_t)OUT_F * IN_F) / (256 * 32);   // 8192

// ── Scratch (device globals; no allocation) ──────────────────────────────
__device__ __half g_X16[(size_t)MROWS * IN_F];
__device__ __half g_W16[(size_t)OUT_F * IN_F];

// ── PTX helpers (sm_80-level only; family-portable) ──────────────────────
__device__ __forceinline__ uint32_t smem_u32(const void* p) {
    uint32_t a;
    asm("{ .reg .u64 t; cvta.to.shared.u64 t, %1; cvt.u32.u64 %0, t; }" : "=r"(a) : "l"(p));
    return a;
}
#define CP_ASYNC16(dst, src) \
    asm volatile("cp.async.cg.shared.global [%0], [%1], 16;" :: "r"(dst), "l"(src))
#define CP_COMMIT() asm volatile("cp.async.commit_group;" ::: "memory")
#define CP_WAIT0()  asm volatile("cp.async.wait_group 0;" ::: "memory")

__device__ __forceinline__ void ldsm4(uint32_t& r0, uint32_t& r1, uint32_t& r2, uint32_t& r3,
                                      uint32_t addr) {
    asm volatile("ldmatrix.sync.aligned.m8n8.x4.shared.b16 {%0,%1,%2,%3}, [%4];"
                 : "=r"(r0), "=r"(r1), "=r"(r2), "=r"(r3) : "r"(addr));
}
#define HMMA(c, a0, a1, a2, a3, b0, b1)                                       \
    asm volatile("mma.sync.aligned.m16n8k16.row.col.f32.f16.f16.f32 "         \
                 "{%0,%1,%2,%3},{%4,%5,%6,%7},{%8,%9},{%0,%1,%2,%3};"         \
                 : "+f"((c)[0]), "+f"((c)[1]), "+f"((c)[2]), "+f"((c)[3])     \
                 : "r"(a0), "r"(a1), "r"(a2), "r"(a3), "r"(b0), "r"(b1))

// swizzled byte offset of (row, 16B-chunk) inside a rows x 128B tile
__device__ __forceinline__ uint32_t swz(uint32_t row, uint32_t chunk) {
    return row * 128u + ((chunk ^ (row & 7u)) << 4);
}

// ── Combined prep: x fp32->fp16, W16 = ternary * fp16(scale) ─────────────
__global__ void prep_kernel(const float* __restrict__ x,
                            const int* __restrict__ tern,
                            const float* __restrict__ scales) {
    int b = blockIdx.x;
    if (b < XBLOCKS) {
        size_t i = ((size_t)b * blockDim.x + threadIdx.x) * 16;
        const float4* x4 = reinterpret_cast<const float4*>(x + i);
        float4 v4[4];
#pragma unroll
        for (int q = 0; q < 4; q++) v4[q] = x4[q];      // 4 independent 16B loads
        union { __half h[16]; uint4 u[2]; } o;
#pragma unroll
        for (int q = 0; q < 4; q++) {
            o.h[q * 4 + 0] = __float2half(v4[q].x);
            o.h[q * 4 + 1] = __float2half(v4[q].y);
            o.h[q * 4 + 2] = __float2half(v4[q].z);
            o.h[q * 4 + 3] = __float2half(v4[q].w);
        }
        uint4* dst = reinterpret_cast<uint4*>(&g_X16[i]);
        dst[0] = o.u[0];
        dst[1] = o.u[1];
    } else {
        size_t i = ((size_t)(b - XBLOCKS) * blockDim.x + threadIdx.x) * 32;
        const int4* t4 = reinterpret_cast<const int4*>(tern + i);
        int4 t[8];
#pragma unroll
        for (int q = 0; q < 8; q++) t[q] = t4[q];       // 8 independent 16B loads
        // all 32 elems lie in one 128-wide scale group (i is a multiple of 32)
        float sf = __half2float(__float2half(scales[i >> 7]));
        union { __half h[32]; uint4 u[4]; } o;
#pragma unroll
        for (int q = 0; q < 8; q++) {
            o.h[q * 4 + 0] = __float2half(sf * (float)t[q].x);  // exact: t in {-1,0,1}
            o.h[q * 4 + 1] = __float2half(sf * (float)t[q].y);
            o.h[q * 4 + 2] = __float2half(sf * (float)t[q].z);
            o.h[q * 4 + 3] = __float2half(sf * (float)t[q].w);
        }
        uint4* dst = reinterpret_cast<uint4*>(&g_W16[i]);
#pragma unroll
        for (int q = 0; q < 4; q++) dst[q] = o.u[q];
    }
}

// ── GEMM: out[M,N] = X16 @ W16^T, fp32 accum in HMMA ─────────────────────
// Pipeline: wait_group0+sync makes stages it AND it+1 readable each iter;
// register fragments double-buffered so ldsm for step j+1 overlaps HMMAs of j,
// including across the k-iteration boundary.
extern __shared__ __align__(128) char smem_raw[];

__global__ void __launch_bounds__(256, 2) qsgd_gemm(float* __restrict__ out)
{
    uint32_t sb = smem_u32(smem_raw);

    int tid = threadIdx.x, lane = tid & 31, wid = tid >> 5;
    int wm = wid & 1, wn = wid >> 1;          // warp grid 2(m) x 4(n): warp tile 64x32
    int gID = lane >> 2, tig = lane & 3;
    int mt0 = blockIdx.x, nt0 = blockIdx.y;   // m fastest in grid

    // ---- cp.async addressing: thread t -> row (t>>3) + 32j, chunk t&7 (bytes)
    int ld_row = tid >> 3, ld_chunk = tid & 7;
    const int8_t* gA = reinterpret_cast<const int8_t*>(g_X16) +
                       (size_t)(mt0 * BM + ld_row) * (IN_F * 2) + ld_chunk * 16;
    const int8_t* gB = reinterpret_cast<const int8_t*>(g_W16) +
                       (size_t)(nt0 * BN + ld_row) * (IN_F * 2) + ld_chunk * 16;
    uint32_t st_off[4];
#pragma unroll
    for (int j = 0; j < 4; j++) st_off[j] = swz(ld_row + 32 * j, ld_chunk);

    // ---- ldmatrix per-lane address components
    uint32_t a_row_base = wm * 64 + (lane & 15);
    uint32_t a_cbit = (uint32_t)(lane >> 4);
    uint32_t b_row_base = wn * 32 + (lane & 7) + ((lane >> 4) & 1) * 8;
    uint32_t b_cbit = (uint32_t)((lane >> 3) & 1);

    float fa[4][4][4];
#pragma unroll
    for (int mt = 0; mt < 4; mt++)
#pragma unroll
        for (int nt = 0; nt < 4; nt++)
#pragma unroll
            for (int r = 0; r < 4; r++) fa[mt][nt][r] = 0.0f;

    // fragment double buffers
    uint32_t af[2][4][4];
    uint32_t bf[2][4][2];

    // helper: load one k16-step's fragments from (sA, sB) at chunk-step pks
#define LOAD_FRAGS(buf, sA_, sB_, pks)                                              \
    do {                                                                            \
        _Pragma("unroll")                                                           \
        for (int mt = 0; mt < 4; mt++) {                                            \
            uint32_t row = a_row_base + mt * 16;                                    \
            uint32_t addr = (sA_) + row * 128u +                                    \
                            (((2u * (pks) + a_cbit) ^ (row & 7u)) << 4);            \
            ldsm4(af[buf][mt][0], af[buf][mt][1], af[buf][mt][2], af[buf][mt][3],   \
                  addr);                                                            \
        }                                                                           \
        _Pragma("unroll")                                                           \
        for (int nb = 0; nb < 2; nb++) {                                            \
            uint32_t row = b_row_base + nb * 16;                                    \
            uint32_t addr = (sB_) + row * 128u +                                    \
                            (((2u * (pks) + b_cbit) ^ (row & 7u)) << 4);            \
            uint32_t r0, r1, r2, r3;                                                \
            ldsm4(r0, r1, r2, r3, addr);                                            \
            bf[buf][nb * 2 + 0][0] = r0; bf[buf][nb * 2 + 0][1] = r1;               \
            bf[buf][nb * 2 + 1][0] = r2; bf[buf][nb * 2 + 1][1] = r3;               \
        }                                                                           \
    } while (0)

    // ---- prologue: commit stages 0,1
#pragma unroll
    for (int p = 0; p < 2; p++) {
        uint32_t s_a = sb + p * STAGE_BYTES;
        size_t kb = (size_t)p * (BK * 2);
#pragma unroll
        for (int j = 0; j < 4; j++) {
            size_t go = (size_t)(32 * j) * (IN_F * 2) + kb;
            CP_ASYNC16(s_a + st_off[j],          gA + go);
            CP_ASYNC16(s_a + A_TILE + st_off[j], gB + go);
        }
        CP_COMMIT();
    }
    CP_WAIT0();
    __syncthreads();               // stages 0 and 1 now readable by all threads

    // preload (stage 0, ks=0) into buffer 0
    LOAD_FRAGS(0, sb, sb + A_TILE, 0u);

    // ---- main loop
    for (int it = 0; it < KITERS; it++) {
        // issue stage it+2 into buffer (it+2)%3 (readers finished last iter; sync passed)
        if (it + 2 < KITERS) {
            uint32_t s_a = sb + ((it + 2) % STAGES) * STAGE_BYTES;
            size_t kb = (size_t)(it + 2) * (BK * 2);
#pragma unroll
            for (int j = 0; j < 4; j++) {
                size_t go = (size_t)(32 * j) * (IN_F * 2) + kb;
                CP_ASYNC16(s_a + st_off[j],          gA + go);
                CP_ASYNC16(s_a + A_TILE + st_off[j], gB + go);
            }
        }
        CP_COMMIT();

        uint32_t sA = sb + (it % STAGES) * STAGE_BYTES;
        uint32_t sB = sA + A_TILE;
        uint32_t sAn = sb + ((it + 1) % STAGES) * STAGE_BYTES;  // readable (wait0+sync)
        uint32_t sBn = sAn + A_TILE;

        // 4 k16 steps; prefetch step j+1 (or next iter's step 0) during HMMAs of j
#pragma unroll
        for (int ks = 0; ks < 4; ks++) {
            int cur = ks & 1, nxt = cur ^ 1;
            if (ks < 3) {
                LOAD_FRAGS(nxt, sA, sB, (uint32_t)(ks + 1));
            } else {
                LOAD_FRAGS(nxt, sAn, sBn, 0u);   // (it+1, ks=0); dead on last iter
            }
#pragma unroll
            for (int mt = 0; mt < 4; mt++)
#pragma unroll
                for (int nt = 0; nt < 4; nt++)
                    HMMA(fa[mt][nt], af[cur][mt][0], af[cur][mt][1],
                         af[cur][mt][2], af[cur][mt][3],
                         bf[cur][nt][0], bf[cur][nt][1]);
        }

        // retire stage it+2's group (one full iteration in flight) + free buffer
        if (it + 1 < KITERS) {
            CP_WAIT0();
            __syncthreads();
        }
    }
#undef LOAD_FRAGS

    // ---- epilogue
#pragma unroll
    for (int mt = 0; mt < 4; mt++)
#pragma unroll
        for (int rr = 0; rr < 2; rr++) {
            int m_g = mt0 * BM + wm * 64 + mt * 16 + gID + rr * 8;
            float* op = out + (size_t)m_g * OUT_F + nt0 * BN + wn * 32 + tig * 2;
#pragma unroll
            for (int nt = 0; nt < 4; nt++) {
                float2 v;
                v.x = fa[mt][nt][rr * 2 + 0];
                v.y = fa[mt][nt][rr * 2 + 1];
                *reinterpret_cast<float2*>(op + nt * 8) = v;
            }
        }
}

// ── Host ─────────────────────────────────────────────────────────────────
extern "C" void kernel_launch(void* const* d_in, const int* in_sizes, int n_in,
                              void* d_out, int out_size) {
    const float* x      = (const float*)d_in[0];
    const int*   tern   = (const int*)d_in[1];
    const float* scales = (const float*)d_in[2];
    float* out = (float*)d_out;

    prep_kernel<<<XBLOCKS + WBLOCKS, 256>>>(x, tern, scales);

    cudaFuncSetAttribute((const void*)qsgd_gemm,
                         cudaFuncAttributeMaxDynamicSharedMemorySize, SMEM_TOTAL);
    // grid: x = M tiles (fastest) so concurrent CTAs share W tiles via L2
    qsgd_gemm<<<dim3(MROWS / BM, OUT_F / BN), 256, SMEM_TOTAL>>>(out);
}